// round 7
// baseline (speedup 1.0000x reference)
#include <cuda_runtime.h>
#include <math.h>
#include <stdint.h>

#define BB   2
#define SS   2048
#define DD   768
#define HH   12
#define DH   64
#define TT   64
#define RR   50
#define MR   (BB*SS)      /* 4096 rows */
#define FF   3072

// dynamic smem for tgemm: 2 x (A 4096 + B 4096) uints
#define AREG 4096
#define DSMEM_U (4*AREG)
#define DSMEM_B (DSMEM_U*4)

// attention smem: Q 8192 + K 4096 + V 4096 + P 8192 uints = 96KB
#define ASM_U  24576
#define ASM_B  (ASM_U*4)

// ---------------- scratch (static device arrays, allowed) ----------------
__device__ float g_q   [MR*DD];
__device__ float g_k   [MR*DD];
__device__ float g_v   [MR*DD];
__device__ float g_ctx [MR*DD];
__device__ float g_tmp [MR*DD];
__device__ float g_x1  [MR*DD];
__device__ float g_x2  [MR*DD];
__device__ float g_tagk[TT*DD];
__device__ float g_tagv[TT*DD];
__device__ float g_int [MR*FF];
__device__ float g_wt  [6*DD*DD + 2*DD*FF];   // transposed weights

static __device__ __forceinline__ uint32_t f2tf32(float x) {
    uint32_t y;
    asm("cvt.rna.tf32.f32 %0, %1;" : "=r"(y) : "f"(x));
    return y;
}

#define MMA_TF32(d, a, b) \
    asm volatile( \
        "mma.sync.aligned.m16n8k8.row.col.f32.tf32.tf32.f32 " \
        "{%0,%1,%2,%3}, {%4,%5,%6,%7}, {%8,%9}, {%0,%1,%2,%3};" \
        : "+f"((d)[0]), "+f"((d)[1]), "+f"((d)[2]), "+f"((d)[3]) \
        : "r"((a).x), "r"((a).y), "r"((a).z), "r"((a).w), \
          "r"((b).x), "r"((b).y))

// Stage one 128x32 A chunk + 128x32 B chunk into fragment-permuted smem.
// A block (m16 x k8) = 128 uints at blk*128, intra-block offset XOR (blk&7)*4.
// B block (n8 x k8) = 64 uints at blk*64, same XOR swizzle.
static __device__ __forceinline__ void stage_chunk(
    uint32_t* __restrict__ sAp, uint32_t* __restrict__ sBp,
    const float4* ra, const float4* rb, int tid)
{
    #pragma unroll
    for (int u = 0; u < 4; ++u) {
        const int idx  = tid + 256 * u;
        const int row  = idx >> 3;            // 0..127
        const int colb = (idx & 7) * 4;       // 0,4,...,28
        {   // A: fragment m16n8k8, 4 regs/lane
            const int blk   = (row >> 4) * 4 + (colb >> 3);
            const int reg   = ((row & 15) >> 3) + 2 * ((colb & 7) >> 2);
            const int rbase = (row & 7) * 16 + reg;
            const int s     = (blk & 7) * 4;
            const float fv[4] = {ra[u].x, ra[u].y, ra[u].z, ra[u].w};
            #pragma unroll
            for (int i = 0; i < 4; ++i)
                sAp[blk * 128 + ((rbase + i * 4) ^ s)] = f2tf32(fv[i]);
        }
        {   // B: 2 regs/lane
            const int blk   = (row >> 3) * 4 + (colb >> 3);
            const int reg   = (colb & 7) >> 2;
            const int rbase = (row & 7) * 8 + reg;
            const int s     = (blk & 7) * 4;
            const float fv[4] = {rb[u].x, rb[u].y, rb[u].z, rb[u].w};
            #pragma unroll
            for (int i = 0; i < 4; ++i)
                sBp[blk * 64 + ((rbase + i * 2) ^ s)] = f2tf32(fv[i]);
        }
    }
}

// ---------------- weight transpose: W[K,N] -> Wt[N,K] ----------------
__global__ __launch_bounds__(256) void transpose_kernel(
    const float* __restrict__ W, float* __restrict__ Wt, int K, int N)
{
    __shared__ float t[32][33];
    const int kb = blockIdx.y * 32, nb = blockIdx.x * 32;
    const int x = threadIdx.x, y = threadIdx.y;
    #pragma unroll
    for (int dy = 0; dy < 32; dy += 8)
        t[y + dy][x] = W[(size_t)(kb + y + dy) * N + nb + x];
    __syncthreads();
    #pragma unroll
    for (int dy = 0; dy < 32; dy += 8)
        Wt[(size_t)(nb + y + dy) * K + kb + x] = t[x][y + dy];
}

// ---------------- tf32 mma.sync GEMM: C = A[MxK] @ Wt[NxK]^T + bias (+epi) ----------------
template<int EPI>
__global__ __launch_bounds__(256) void tgemm_kernel(
    const float* __restrict__ A, const float* __restrict__ Wt,
    const float* __restrict__ bias, const float* __restrict__ res,
    float* __restrict__ C, int M, int N, int K)
{
    extern __shared__ uint32_t smem_u[];
    uint32_t* sA[2] = { smem_u,            smem_u + AREG     };
    uint32_t* sB[2] = { smem_u + 2*AREG,   smem_u + 3*AREG   };

    const int tid  = threadIdx.x;
    const int wid  = tid >> 5, lane = tid & 31;
    const int bn   = blockIdx.x * 128, bm = blockIdx.y * 128;
    const int wm16 = (wid >> 2) * 4;
    const int wn8  = (wid & 3) * 4;

    float acc[4][4][4] = {};
    float4 ra[4], rb[4];

    const int NC = K / 32;

    #pragma unroll
    for (int u = 0; u < 4; ++u) {
        const int idx = tid + 256 * u;
        const int row = idx >> 3, col = (idx & 7) * 4;
        ra[u] = *(const float4*)&A [(size_t)(bm + row) * K + col];
        rb[u] = *(const float4*)&Wt[(size_t)(bn + row) * K + col];
    }
    stage_chunk(sA[0], sB[0], ra, rb, tid);
    __syncthreads();

    for (int c = 0; c < NC; ++c) {
        const int p = c & 1;
        if (c + 1 < NC) {
            const int k0 = (c + 1) * 32;
            #pragma unroll
            for (int u = 0; u < 4; ++u) {
                const int idx = tid + 256 * u;
                const int row = idx >> 3, col = (idx & 7) * 4;
                ra[u] = *(const float4*)&A [(size_t)(bm + row) * K + k0 + col];
                rb[u] = *(const float4*)&Wt[(size_t)(bn + row) * K + k0 + col];
            }
        }
        #pragma unroll
        for (int k8 = 0; k8 < 4; ++k8) {
            uint4 af[4]; uint2 bf[4];
            #pragma unroll
            for (int t = 0; t < 4; ++t) {
                const int blk = (wm16 + t) * 4 + k8;
                af[t] = *(const uint4*)&sA[p][blk * 128 + ((lane * 4) ^ ((blk & 7) * 4))];
            }
            #pragma unroll
            for (int t = 0; t < 4; ++t) {
                const int blk = (wn8 + t) * 4 + k8;
                bf[t] = *(const uint2*)&sB[p][blk * 64 + ((lane * 2) ^ ((blk & 7) * 4))];
            }
            #pragma unroll
            for (int i = 0; i < 4; ++i)
                #pragma unroll
                for (int j = 0; j < 4; ++j)
                    MMA_TF32(acc[i][j], af[i], bf[j]);
        }
        if (c + 1 < NC) {
            __syncthreads();
            stage_chunk(sA[(c + 1) & 1], sB[(c + 1) & 1], ra, rb, tid);
            __syncthreads();
        }
    }

    #pragma unroll
    for (int i = 0; i < 4; ++i) {
        const int r0 = bm + (wid >> 2) * 64 + i * 16 + (lane >> 2);
        #pragma unroll
        for (int j = 0; j < 4; ++j) {
            const int cb = bn + (wid & 3) * 32 + j * 8 + (lane & 3) * 2;
            float v0 = acc[i][j][0] + bias[cb];
            float v1 = acc[i][j][1] + bias[cb + 1];
            float v2 = acc[i][j][2] + bias[cb];
            float v3 = acc[i][j][3] + bias[cb + 1];
            if (EPI == 1) {
                v0 = 0.5f * v0 * (1.0f + erff(v0 * 0.70710678118654752f));
                v1 = 0.5f * v1 * (1.0f + erff(v1 * 0.70710678118654752f));
                v2 = 0.5f * v2 * (1.0f + erff(v2 * 0.70710678118654752f));
                v3 = 0.5f * v3 * (1.0f + erff(v3 * 0.70710678118654752f));
            }
            if (EPI == 2) {
                v0 += res[(size_t)r0 * N + cb];
                v1 += res[(size_t)r0 * N + cb + 1];
                v2 += res[(size_t)(r0 + 8) * N + cb];
                v3 += res[(size_t)(r0 + 8) * N + cb + 1];
            }
            *(float2*)&C[(size_t)r0 * N + cb]       = make_float2(v0, v1);
            *(float2*)&C[(size_t)(r0 + 8) * N + cb] = make_float2(v2, v3);
        }
    }
}

// ---------------- small fp32 SGEMM (tag K/V projections only) ----------------
template<int EPI>
__global__ __launch_bounds__(256) void sgemm_kernel(
    const float* __restrict__ A, const float* __restrict__ W,
    const float* __restrict__ bias, const float* __restrict__ res,
    float* __restrict__ C, int M, int N, int K)
{
    __shared__ float As[16][64];
    __shared__ float Bs[16][64];
    const int tid = threadIdx.x;
    const int tx = tid & 15, ty = tid >> 4;
    const int bn = blockIdx.x * 64, bm = blockIdx.y * 64;
    const int am = tid >> 2, ak = (tid & 3) * 4;
    const int wk = tid >> 4, wn = (tid & 15) * 4;
    float acc[4][4] = {};
    for (int k0 = 0; k0 < K; k0 += 16) {
        float4 av = *(const float4*)&A[(size_t)(bm + am) * K + k0 + ak];
        As[ak + 0][am] = av.x; As[ak + 1][am] = av.y;
        As[ak + 2][am] = av.z; As[ak + 3][am] = av.w;
        *(float4*)&Bs[wk][wn] = *(const float4*)&W[(size_t)(k0 + wk) * N + bn + wn];
        __syncthreads();
        #pragma unroll
        for (int kk = 0; kk < 16; kk++) {
            float4 a4 = *(const float4*)&As[kk][ty * 4];
            float4 b4 = *(const float4*)&Bs[kk][tx * 4];
            float a[4] = {a4.x, a4.y, a4.z, a4.w};
            float b[4] = {b4.x, b4.y, b4.z, b4.w};
            #pragma unroll
            for (int i = 0; i < 4; i++)
                #pragma unroll
                for (int j = 0; j < 4; j++)
                    acc[i][j] = fmaf(a[i], b[j], acc[i][j]);
        }
        __syncthreads();
    }
    #pragma unroll
    for (int i = 0; i < 4; i++) {
        const int m = bm + ty * 4 + i;
        #pragma unroll
        for (int j = 0; j < 4; j++) {
            const int n = bn + tx * 4 + j;
            float v = acc[i][j] + bias[n];
            if (EPI == 1) v = 0.5f * v * (1.0f + erff(v * 0.70710678118654752f));
            if (EPI == 2) v += res[(size_t)m * N + n];
            C[(size_t)m * N + n] = v;
        }
    }
}

// ---------------- tensor-core flash attention ----------------
// 128-query tile per CTA, 8 warps; warp w owns m16 tile w (16 q rows x all keys).
// Key chunks of 64. QK^T and PV via tf32 m16n8k8; online softmax on fragments.
__global__ __launch_bounds__(256) void attn_mma_kernel(
    const float* __restrict__ Q, const float* __restrict__ K,
    const float* __restrict__ V, float* __restrict__ O,
    int Skv, long long kv_bstride, int band)
{
    extern __shared__ uint32_t sm[];
    uint32_t* sQ = sm;               // 8 m-blk x 8 k-blk x 128 = 8192
    uint32_t* sK = sm + 8192;        // 8 n-blk x 8 k-blk x 64  = 4096
    uint32_t* sV = sm + 12288;       // 4096
    uint32_t* sP = sm + 16384;       // 8192

    const int tid = threadIdx.x, w = tid >> 5, lane = tid & 31;
    const int qt = blockIdx.x * 128, h = blockIdx.y, b = blockIdx.z;

    const float* qbase = Q + ((size_t)b * SS + qt) * DD + h * DH;
    const float* kbase = K + (size_t)b * kv_bstride + h * DH;
    const float* vbase = V + (size_t)b * kv_bstride + h * DH;

    // ---- stage Q (pre-scaled by 1/8) as A-operand blocks ----
    #pragma unroll
    for (int u = 0; u < 8; ++u) {
        const int idx = tid + 256 * u;
        const int row = idx >> 4, colb = (idx & 15) * 4;
        float4 qv = *(const float4*)&qbase[(size_t)row * DD + colb];
        const int blk  = (row >> 4) * 8 + (colb >> 3);
        const int reg  = ((row & 15) >> 3) + 2 * ((colb & 7) >> 2);
        const int base = (row & 7) * 16 + reg;
        const int s    = (blk & 7) * 4;
        const float f[4] = {qv.x, qv.y, qv.z, qv.w};
        #pragma unroll
        for (int i = 0; i < 4; ++i)
            sQ[blk * 128 + ((base + i * 4) ^ s)] = f2tf32(f[i] * 0.125f);
    }

    float m0 = -1e30f, m1 = -1e30f, l0 = 0.0f, l1 = 0.0f;
    float oacc[8][4] = {};
    const int r0 = lane >> 2;        // fragment row within m16 (0..7)
    const int c0 = (lane & 3) * 2;   // fragment col within n8 (accum)

    for (int kt = 0; kt < Skv; kt += 64) {
        __syncthreads();             // prev PV readers done with sK/sV
        // ---- stage K (B: n=key, k=dh) and V (B: n=dh, k=key) ----
        #pragma unroll
        for (int u = 0; u < 4; ++u) {
            const int idx = tid + 256 * u;
            const int row = idx >> 4, colb = (idx & 15) * 4;
            float4 kv = *(const float4*)&kbase[(size_t)(kt + row) * DD + colb];
            float4 vv = *(const float4*)&vbase[(size_t)(kt + row) * DD + colb];
            {   // K
                const int blk  = (row >> 3) * 8 + (colb >> 3);
                const int s    = (blk & 7) * 4;
                const int base = (row & 7) * 8 + ((colb & 7) >> 2);
                const float f[4] = {kv.x, kv.y, kv.z, kv.w};
                #pragma unroll
                for (int i = 0; i < 4; ++i)
                    sK[blk * 64 + ((base + 2 * i) ^ s)] = f2tf32(f[i]);
            }
            {   // V transposed: element (n=col, k=row)
                const int kb    = row >> 3;
                const int s     = kb * 4;
                const int off_k = (row & 3) * 2 + ((row & 7) >> 2);
                const float f[4] = {vv.x, vv.y, vv.z, vv.w};
                #pragma unroll
                for (int i = 0; i < 4; ++i) {
                    const int c = colb + i;
                    sV[((c >> 3) * 8 + kb) * 64 + (((c & 7) * 8 + off_k) ^ s)] = f2tf32(f[i]);
                }
            }
        }
        __syncthreads();

        // ---- QK^T: 16 q x 64 keys per warp ----
        float sacc[8][4] = {};
        #pragma unroll
        for (int kb = 0; kb < 8; ++kb) {
            const int sa = kb * 4;
            uint4 af = *(const uint4*)&sQ[(w * 8 + kb) * 128 + ((lane * 4) ^ sa)];
            #pragma unroll
            for (int j = 0; j < 8; ++j) {
                uint2 bf = *(const uint2*)&sK[(j * 8 + kb) * 64 + ((lane * 2) ^ sa)];
                MMA_TF32(sacc[j], af, bf);
            }
        }

        // ---- band bias (additive +1 inside |dq|<=R) ----
        if (band) {
            const int q0 = qt + w * 16 + r0;
            #pragma unroll
            for (int j = 0; j < 8; ++j) {
                const int kc = kt + j * 8 + c0;
                #pragma unroll
                for (int v = 0; v < 4; ++v) {
                    const int dq = (q0 + ((v >> 1) << 3)) - (kc + (v & 1));
                    if ((unsigned)(dq + RR) <= 2u * RR) sacc[j][v] += 1.0f;
                }
            }
        }

        // ---- online softmax (rows r0, r0+8; cols across 4-lane group) ----
        float mx0 = -1e30f, mx1 = -1e30f;
        #pragma unroll
        for (int j = 0; j < 8; ++j) {
            mx0 = fmaxf(mx0, fmaxf(sacc[j][0], sacc[j][1]));
            mx1 = fmaxf(mx1, fmaxf(sacc[j][2], sacc[j][3]));
        }
        #pragma unroll
        for (int off = 1; off < 4; off <<= 1) {
            mx0 = fmaxf(mx0, __shfl_xor_sync(0xffffffffu, mx0, off, 4));
            mx1 = fmaxf(mx1, __shfl_xor_sync(0xffffffffu, mx1, off, 4));
        }
        const float mn0 = fmaxf(m0, mx0), mn1 = fmaxf(m1, mx1);
        const float cr0 = __expf(m0 - mn0), cr1 = __expf(m1 - mn1);
        float rs0 = 0.0f, rs1 = 0.0f;
        #pragma unroll
        for (int j = 0; j < 8; ++j) {
            sacc[j][0] = __expf(sacc[j][0] - mn0); rs0 += sacc[j][0];
            sacc[j][1] = __expf(sacc[j][1] - mn0); rs0 += sacc[j][1];
            sacc[j][2] = __expf(sacc[j][2] - mn1); rs1 += sacc[j][2];
            sacc[j][3] = __expf(sacc[j][3] - mn1); rs1 += sacc[j][3];
        }
        #pragma unroll
        for (int off = 1; off < 4; off <<= 1) {
            rs0 += __shfl_xor_sync(0xffffffffu, rs0, off, 4);
            rs1 += __shfl_xor_sync(0xffffffffu, rs1, off, 4);
        }
        l0 = l0 * cr0 + rs0; l1 = l1 * cr1 + rs1;
        m0 = mn0; m1 = mn1;
        #pragma unroll
        for (int j = 0; j < 8; ++j) {
            oacc[j][0] *= cr0; oacc[j][1] *= cr0;
            oacc[j][2] *= cr1; oacc[j][3] *= cr1;
        }

        // ---- store P as A-operand (warp-private blocks) ----
        #pragma unroll
        for (int j = 0; j < 8; ++j) {
            const int s = j * 4;
            const int base0 = r0 * 16 + 4 * (c0 & 3) + 2 * (c0 >> 2);
            const int o0 = base0 ^ s;
            const int o1 = (base0 + 4) ^ s;
            uint32_t* bp = &sP[(w * 8 + j) * 128];
            bp[o0]     = f2tf32(sacc[j][0]);
            bp[o0 + 1] = f2tf32(sacc[j][2]);
            bp[o1]     = f2tf32(sacc[j][1]);
            bp[o1 + 1] = f2tf32(sacc[j][3]);
        }
        __syncwarp();

        // ---- PV: o += P @ V ----
        #pragma unroll
        for (int kb = 0; kb < 8; ++kb) {
            const int sa = kb * 4;
            uint4 af = *(const uint4*)&sP[(w * 8 + kb) * 128 + ((lane * 4) ^ sa)];
            #pragma unroll
            for (int j = 0; j < 8; ++j) {
                uint2 bf = *(const uint2*)&sV[(j * 8 + kb) * 64 + ((lane * 2) ^ sa)];
                MMA_TF32(oacc[j], af, bf);
            }
        }
    }

    // ---- epilogue: normalize and store ----
    const float inv0 = 1.0f / l0, inv1 = 1.0f / l1;
    const size_t grow = (size_t)b * SS + qt + w * 16 + r0;
    #pragma unroll
    for (int j = 0; j < 8; ++j) {
        const int col = h * DH + j * 8 + c0;
        *(float2*)&O[grow * DD + col] =
            make_float2(oacc[j][0] * inv0, oacc[j][1] * inv0);
        *(float2*)&O[(grow + 8) * DD + col] =
            make_float2(oacc[j][2] * inv1, oacc[j][3] * inv1);
    }
}

// ---------------- row LayerNorm over D=768 ----------------
__global__ __launch_bounds__(256) void ln_kernel(
    const float* __restrict__ X, const float* __restrict__ gg,
    const float* __restrict__ bb, float* __restrict__ Y)
{
    __shared__ float red[9];
    const int row = blockIdx.x, tid = threadIdx.x;
    const float* x = X + (size_t)row * DD;
    float v0 = x[tid], v1 = x[tid + 256], v2 = x[tid + 512];

    float s = v0 + v1 + v2;
    #pragma unroll
    for (int off = 16; off; off >>= 1) s += __shfl_xor_sync(0xffffffffu, s, off);
    if ((tid & 31) == 0) red[tid >> 5] = s;
    __syncthreads();
    if (tid == 0) { float t = 0; for (int i = 0; i < 8; i++) t += red[i]; red[8] = t; }
    __syncthreads();
    const float mean = red[8] * (1.0f / 768.0f);

    float d0 = v0 - mean, d1 = v1 - mean, d2 = v2 - mean;
    float s2 = d0 * d0 + d1 * d1 + d2 * d2;
    #pragma unroll
    for (int off = 16; off; off >>= 1) s2 += __shfl_xor_sync(0xffffffffu, s2, off);
    __syncthreads();
    if ((tid & 31) == 0) red[tid >> 5] = s2;
    __syncthreads();
    if (tid == 0) { float t = 0; for (int i = 0; i < 8; i++) t += red[i]; red[8] = t; }
    __syncthreads();
    const float rstd = rsqrtf(red[8] * (1.0f / 768.0f) + 1e-12f);

    float* y = Y + (size_t)row * DD;
    y[tid]       = d0 * rstd * gg[tid]       + bb[tid];
    y[tid + 256] = d1 * rstd * gg[tid + 256] + bb[tid + 256];
    y[tid + 512] = d2 * rstd * gg[tid + 512] + bb[tid + 512];
}

// ---------------- host launcher ----------------
extern "C" void kernel_launch(void* const* d_in, const int* in_sizes, int n_in,
                              void* d_out, int out_size)
{
    const float* X      = (const float*)d_in[0];
    const float* tag    = (const float*)d_in[1];
    const float* sa_wq  = (const float*)d_in[2];  const float* sa_bq = (const float*)d_in[3];
    const float* sa_wk  = (const float*)d_in[4];  const float* sa_bk = (const float*)d_in[5];
    const float* sa_wv  = (const float*)d_in[6];  const float* sa_bv = (const float*)d_in[7];
    const float* sa_wo  = (const float*)d_in[8];  const float* sa_bo = (const float*)d_in[9];
    const float* sa_lg  = (const float*)d_in[10]; const float* sa_lb = (const float*)d_in[11];
    const float* ca_wq  = (const float*)d_in[12]; const float* ca_bq = (const float*)d_in[13];
    const float* ca_wk  = (const float*)d_in[14]; const float* ca_bk = (const float*)d_in[15];
    const float* ca_wv  = (const float*)d_in[16]; const float* ca_bv = (const float*)d_in[17];
    const float* ca_wo  = (const float*)d_in[18]; const float* ca_bo = (const float*)d_in[19];
    const float* ca_lg  = (const float*)d_in[20]; const float* ca_lb = (const float*)d_in[21];
    const float* ff_w1  = (const float*)d_in[22]; const float* ff_b1 = (const float*)d_in[23];
    const float* ff_w2  = (const float*)d_in[24]; const float* ff_b2 = (const float*)d_in[25];
    const float* ff_lg  = (const float*)d_in[26]; const float* ff_lb = (const float*)d_in[27];

    float *q, *k, *v, *ctx, *tmp, *x1, *x2, *tk, *tv, *it, *wt;
    cudaGetSymbolAddress((void**)&q,   g_q);
    cudaGetSymbolAddress((void**)&k,   g_k);
    cudaGetSymbolAddress((void**)&v,   g_v);
    cudaGetSymbolAddress((void**)&ctx, g_ctx);
    cudaGetSymbolAddress((void**)&tmp, g_tmp);
    cudaGetSymbolAddress((void**)&x1,  g_x1);
    cudaGetSymbolAddress((void**)&x2,  g_x2);
    cudaGetSymbolAddress((void**)&tk,  g_tagk);
    cudaGetSymbolAddress((void**)&tv,  g_tagv);
    cudaGetSymbolAddress((void**)&it,  g_int);
    cudaGetSymbolAddress((void**)&wt,  g_wt);

    const size_t WSZ = (size_t)DD * DD;
    float* wtq   = wt;
    float* wtk   = wt + WSZ;
    float* wtv   = wt + 2 * WSZ;
    float* wto   = wt + 3 * WSZ;
    float* wtcq  = wt + 4 * WSZ;
    float* wtcao = wt + 5 * WSZ;
    float* wtff1 = wt + 6 * WSZ;
    float* wtff2 = wtff1 + (size_t)FF * DD;

    cudaFuncSetAttribute((const void*)tgemm_kernel<0>, cudaFuncAttributeMaxDynamicSharedMemorySize, DSMEM_B);
    cudaFuncSetAttribute((const void*)tgemm_kernel<1>, cudaFuncAttributeMaxDynamicSharedMemorySize, DSMEM_B);
    cudaFuncSetAttribute((const void*)tgemm_kernel<2>, cudaFuncAttributeMaxDynamicSharedMemorySize, DSMEM_B);
    cudaFuncSetAttribute((const void*)attn_mma_kernel,  cudaFuncAttributeMaxDynamicSharedMemorySize, ASM_B);

    // ---- weight transposes ([K,N] -> [N,K]) ----
    const dim3 tb(32, 8);
    transpose_kernel<<<dim3(DD/32, DD/32), tb>>>(sa_wq, wtq,   DD, DD);
    transpose_kernel<<<dim3(DD/32, DD/32), tb>>>(sa_wk, wtk,   DD, DD);
    transpose_kernel<<<dim3(DD/32, DD/32), tb>>>(sa_wv, wtv,   DD, DD);
    transpose_kernel<<<dim3(DD/32, DD/32), tb>>>(sa_wo, wto,   DD, DD);
    transpose_kernel<<<dim3(DD/32, DD/32), tb>>>(ca_wq, wtcq,  DD, DD);
    transpose_kernel<<<dim3(DD/32, DD/32), tb>>>(ca_wo, wtcao, DD, DD);
    transpose_kernel<<<dim3(FF/32, DD/32), tb>>>(ff_w1, wtff1, DD, FF);
    transpose_kernel<<<dim3(DD/32, FF/32), tb>>>(ff_w2, wtff2, FF, DD);

    const dim3 gp (DD / 128, MR / 128);          // (6, 32)
    const dim3 gf (FF / 128, MR / 128);          // (24, 32)
    const dim3 gtag(DD / 64, 1);
    const dim3 gat (SS / 128, HH, BB);           // (16, 12, 2)

    // ---- self attention ----
    tgemm_kernel<0><<<gp, 256, DSMEM_B>>>(X,  wtq, sa_bq, nullptr, q, MR, DD, DD);
    tgemm_kernel<0><<<gp, 256, DSMEM_B>>>(X,  wtk, sa_bk, nullptr, k, MR, DD, DD);
    tgemm_kernel<0><<<gp, 256, DSMEM_B>>>(X,  wtv, sa_bv, nullptr, v, MR, DD, DD);
    attn_mma_kernel<<<gat, 256, ASM_B>>>(q, k, v, ctx, SS, (long long)SS * DD, 1);
    tgemm_kernel<2><<<gp, 256, DSMEM_B>>>(ctx, wto, sa_bo, X, tmp, MR, DD, DD);
    ln_kernel<<<MR, 256>>>(tmp, sa_lg, sa_lb, x1);

    // ---- cross attention (tags shared across batch) ----
    tgemm_kernel<0><<<gp, 256, DSMEM_B>>>(x1, wtcq, ca_bq, nullptr, q, MR, DD, DD);
    sgemm_kernel<0><<<gtag, 256>>>(tag, ca_wk, ca_bk, nullptr, tk, TT, DD, DD);
    sgemm_kernel<0><<<gtag, 256>>>(tag, ca_wv, ca_bv, nullptr, tv, TT, DD, DD);
    attn_mma_kernel<<<gat, 256, ASM_B>>>(q, tk, tv, ctx, TT, 0LL, 0);
    tgemm_kernel<2><<<gp, 256, DSMEM_B>>>(ctx, wtcao, ca_bo, x1, tmp, MR, DD, DD);
    ln_kernel<<<MR, 256>>>(tmp, ca_lg, ca_lb, x2);

    // ---- FFN ----
    tgemm_kernel<1><<<gf, 256, DSMEM_B>>>(x2, wtff1, ff_b1, nullptr, it, MR, FF, DD);
    tgemm_kernel<2><<<gp, 256, DSMEM_B>>>(it, wtff2, ff_b2, x2, tmp, MR, DD, FF);
    ln_kernel<<<MR, 256>>>(tmp, ff_lg, ff_lb, (float*)d_out);
}

// round 8
// speedup vs baseline: 1.4640x; 1.4640x over previous
#include <cuda_runtime.h>
#include <math.h>
#include <stdint.h>

#define BB   2
#define SS   2048
#define DD   768
#define HH   12
#define DH   64
#define TT   64
#define RR   50
#define MR   (BB*SS)      /* 4096 rows */
#define FF   3072

// dynamic smem for tgemm: 2 x (A 4096 + B 4096) uints
#define AREG 4096
#define DSMEM_U (4*AREG)
#define DSMEM_B (DSMEM_U*4)

// attention smem: Q 8192 + K 4096 + V 4096 + P 8192 uints = 96KB
#define ASM_U  24576
#define ASM_B  (ASM_U*4)

// ---------------- scratch (static device arrays, allowed) ----------------
__device__ float g_q   [MR*DD];
__device__ float g_k   [MR*DD];
__device__ float g_v   [MR*DD];
__device__ float g_ctx [MR*DD];
__device__ float g_tmp [MR*DD];
__device__ float g_x1  [MR*DD];
__device__ float g_x2  [MR*DD];
__device__ float g_tagk[TT*DD];
__device__ float g_tagv[TT*DD];
__device__ float g_int [MR*FF];
__device__ float g_wt  [6*DD*DD + 2*DD*FF];   // transposed weights

static __device__ __forceinline__ uint32_t f2tf32(float x) {
    uint32_t y;
    asm("cvt.rna.tf32.f32 %0, %1;" : "=r"(y) : "f"(x));
    return y;
}

#define MMA_TF32(d, a, b) \
    asm volatile( \
        "mma.sync.aligned.m16n8k8.row.col.f32.tf32.tf32.f32 " \
        "{%0,%1,%2,%3}, {%4,%5,%6,%7}, {%8,%9}, {%0,%1,%2,%3};" \
        : "+f"((d)[0]), "+f"((d)[1]), "+f"((d)[2]), "+f"((d)[3]) \
        : "r"((a).x), "r"((a).y), "r"((a).z), "r"((a).w), \
          "r"((b).x), "r"((b).y))

// Stage one 128x32 A chunk + 128x32 B chunk into fragment-permuted smem.
// A block (m16 x k8) = 128 uints at blk*128, intra-block offset XOR (blk&7)*4.
// B block (n8 x k8) = 64 uints at blk*64, same XOR swizzle.
static __device__ __forceinline__ void stage_chunk(
    uint32_t* __restrict__ sAp, uint32_t* __restrict__ sBp,
    const float4* ra, const float4* rb, int tid)
{
    #pragma unroll
    for (int u = 0; u < 4; ++u) {
        const int idx  = tid + 256 * u;
        const int row  = idx >> 3;            // 0..127
        const int colb = (idx & 7) * 4;       // 0,4,...,28
        {   // A: fragment m16n8k8, 4 regs/lane
            const int blk   = (row >> 4) * 4 + (colb >> 3);
            const int reg   = ((row & 15) >> 3) + 2 * ((colb & 7) >> 2);
            const int rbase = (row & 7) * 16 + reg;
            const int s     = (blk & 7) * 4;
            const float fv[4] = {ra[u].x, ra[u].y, ra[u].z, ra[u].w};
            #pragma unroll
            for (int i = 0; i < 4; ++i)
                sAp[blk * 128 + ((rbase + i * 4) ^ s)] = f2tf32(fv[i]);
        }
        {   // B: 2 regs/lane
            const int blk   = (row >> 3) * 4 + (colb >> 3);
            const int reg   = (colb & 7) >> 2;
            const int rbase = (row & 7) * 8 + reg;
            const int s     = (blk & 7) * 4;
            const float fv[4] = {rb[u].x, rb[u].y, rb[u].z, rb[u].w};
            #pragma unroll
            for (int i = 0; i < 4; ++i)
                sBp[blk * 64 + ((rbase + i * 2) ^ s)] = f2tf32(fv[i]);
        }
    }
}

// ---------------- weight transpose: W[K,N] -> Wt[N,K] ----------------
__global__ __launch_bounds__(256) void transpose_kernel(
    const float* __restrict__ W, float* __restrict__ Wt, int K, int N)
{
    __shared__ float t[32][33];
    const int kb = blockIdx.y * 32, nb = blockIdx.x * 32;
    const int x = threadIdx.x, y = threadIdx.y;
    #pragma unroll
    for (int dy = 0; dy < 32; dy += 8)
        t[y + dy][x] = W[(size_t)(kb + y + dy) * N + nb + x];
    __syncthreads();
    #pragma unroll
    for (int dy = 0; dy < 32; dy += 8)
        Wt[(size_t)(nb + y + dy) * K + kb + x] = t[x][y + dy];
}

// ---------------- tf32 mma.sync GEMM: C = A[MxK] @ Wt[NxK]^T + bias (+epi) ----------------
template<int EPI>
__global__ __launch_bounds__(256) void tgemm_kernel(
    const float* __restrict__ A, const float* __restrict__ Wt,
    const float* __restrict__ bias, const float* __restrict__ res,
    float* __restrict__ C, int M, int N, int K)
{
    extern __shared__ uint32_t smem_u[];
    uint32_t* sA[2] = { smem_u,            smem_u + AREG     };
    uint32_t* sB[2] = { smem_u + 2*AREG,   smem_u + 3*AREG   };

    const int tid  = threadIdx.x;
    const int wid  = tid >> 5, lane = tid & 31;
    const int bn   = blockIdx.x * 128, bm = blockIdx.y * 128;
    const int wm16 = (wid >> 2) * 4;
    const int wn8  = (wid & 3) * 4;

    float acc[4][4][4] = {};
    float4 ra[4], rb[4];

    const int NC = K / 32;

    #pragma unroll
    for (int u = 0; u < 4; ++u) {
        const int idx = tid + 256 * u;
        const int row = idx >> 3, col = (idx & 7) * 4;
        ra[u] = *(const float4*)&A [(size_t)(bm + row) * K + col];
        rb[u] = *(const float4*)&Wt[(size_t)(bn + row) * K + col];
    }
    stage_chunk(sA[0], sB[0], ra, rb, tid);
    __syncthreads();

    for (int c = 0; c < NC; ++c) {
        const int p = c & 1;
        if (c + 1 < NC) {
            const int k0 = (c + 1) * 32;
            #pragma unroll
            for (int u = 0; u < 4; ++u) {
                const int idx = tid + 256 * u;
                const int row = idx >> 3, col = (idx & 7) * 4;
                ra[u] = *(const float4*)&A [(size_t)(bm + row) * K + k0 + col];
                rb[u] = *(const float4*)&Wt[(size_t)(bn + row) * K + k0 + col];
            }
        }
        #pragma unroll
        for (int k8 = 0; k8 < 4; ++k8) {
            uint4 af[4]; uint2 bf[4];
            #pragma unroll
            for (int t = 0; t < 4; ++t) {
                const int blk = (wm16 + t) * 4 + k8;
                af[t] = *(const uint4*)&sA[p][blk * 128 + ((lane * 4) ^ ((blk & 7) * 4))];
            }
            #pragma unroll
            for (int t = 0; t < 4; ++t) {
                const int blk = (wn8 + t) * 4 + k8;
                bf[t] = *(const uint2*)&sB[p][blk * 64 + ((lane * 2) ^ ((blk & 7) * 4))];
            }
            #pragma unroll
            for (int i = 0; i < 4; ++i)
                #pragma unroll
                for (int j = 0; j < 4; ++j)
                    MMA_TF32(acc[i][j], af[i], bf[j]);
        }
        if (c + 1 < NC) {
            __syncthreads();
            stage_chunk(sA[(c + 1) & 1], sB[(c + 1) & 1], ra, rb, tid);
            __syncthreads();
        }
    }

    #pragma unroll
    for (int i = 0; i < 4; ++i) {
        const int r0 = bm + (wid >> 2) * 64 + i * 16 + (lane >> 2);
        #pragma unroll
        for (int j = 0; j < 4; ++j) {
            const int cb = bn + (wid & 3) * 32 + j * 8 + (lane & 3) * 2;
            float v0 = acc[i][j][0] + bias[cb];
            float v1 = acc[i][j][1] + bias[cb + 1];
            float v2 = acc[i][j][2] + bias[cb];
            float v3 = acc[i][j][3] + bias[cb + 1];
            if (EPI == 1) {
                v0 = 0.5f * v0 * (1.0f + erff(v0 * 0.70710678118654752f));
                v1 = 0.5f * v1 * (1.0f + erff(v1 * 0.70710678118654752f));
                v2 = 0.5f * v2 * (1.0f + erff(v2 * 0.70710678118654752f));
                v3 = 0.5f * v3 * (1.0f + erff(v3 * 0.70710678118654752f));
            }
            if (EPI == 2) {
                v0 += res[(size_t)r0 * N + cb];
                v1 += res[(size_t)r0 * N + cb + 1];
                v2 += res[(size_t)(r0 + 8) * N + cb];
                v3 += res[(size_t)(r0 + 8) * N + cb + 1];
            }
            *(float2*)&C[(size_t)r0 * N + cb]       = make_float2(v0, v1);
            *(float2*)&C[(size_t)(r0 + 8) * N + cb] = make_float2(v2, v3);
        }
    }
}

// ---------------- small fp32 SGEMM (tag K/V projections only) ----------------
template<int EPI>
__global__ __launch_bounds__(256) void sgemm_kernel(
    const float* __restrict__ A, const float* __restrict__ W,
    const float* __restrict__ bias, const float* __restrict__ res,
    float* __restrict__ C, int M, int N, int K)
{
    __shared__ float As[16][64];
    __shared__ float Bs[16][64];
    const int tid = threadIdx.x;
    const int tx = tid & 15, ty = tid >> 4;
    const int bn = blockIdx.x * 64, bm = blockIdx.y * 64;
    const int am = tid >> 2, ak = (tid & 3) * 4;
    const int wk = tid >> 4, wn = (tid & 15) * 4;
    float acc[4][4] = {};
    for (int k0 = 0; k0 < K; k0 += 16) {
        float4 av = *(const float4*)&A[(size_t)(bm + am) * K + k0 + ak];
        As[ak + 0][am] = av.x; As[ak + 1][am] = av.y;
        As[ak + 2][am] = av.z; As[ak + 3][am] = av.w;
        *(float4*)&Bs[wk][wn] = *(const float4*)&W[(size_t)(k0 + wk) * N + bn + wn];
        __syncthreads();
        #pragma unroll
        for (int kk = 0; kk < 16; kk++) {
            float4 a4 = *(const float4*)&As[kk][ty * 4];
            float4 b4 = *(const float4*)&Bs[kk][tx * 4];
            float a[4] = {a4.x, a4.y, a4.z, a4.w};
            float b[4] = {b4.x, b4.y, b4.z, b4.w};
            #pragma unroll
            for (int i = 0; i < 4; i++)
                #pragma unroll
                for (int j = 0; j < 4; j++)
                    acc[i][j] = fmaf(a[i], b[j], acc[i][j]);
        }
        __syncthreads();
    }
    #pragma unroll
    for (int i = 0; i < 4; i++) {
        const int m = bm + ty * 4 + i;
        #pragma unroll
        for (int j = 0; j < 4; j++) {
            const int n = bn + tx * 4 + j;
            float v = acc[i][j] + bias[n];
            if (EPI == 1) v = 0.5f * v * (1.0f + erff(v * 0.70710678118654752f));
            if (EPI == 2) v += res[(size_t)m * N + n];
            C[(size_t)m * N + n] = v;
        }
    }
}

// ---------------- tensor-core flash attention (with K/V prefetch) ----------------
// 128-query tile per CTA, 8 warps; warp w owns m16 tile w (16 q rows x all keys).
// Key chunks of 64. QK^T and PV via tf32 m16n8k8; online softmax on fragments.
// Next chunk's K/V global loads are issued right after staging so compute hides them.
__global__ __launch_bounds__(256) void attn_mma_kernel(
    const float* __restrict__ Q, const float* __restrict__ K,
    const float* __restrict__ V, float* __restrict__ O,
    int Skv, long long kv_bstride, int band)
{
    extern __shared__ uint32_t sm[];
    uint32_t* sQ = sm;               // 8 m-blk x 8 k-blk x 128 = 8192
    uint32_t* sK = sm + 8192;        // 8 n-blk x 8 k-blk x 64  = 4096
    uint32_t* sV = sm + 12288;       // 4096
    uint32_t* sP = sm + 16384;       // 8192

    const int tid = threadIdx.x, w = tid >> 5, lane = tid & 31;
    const int qt = blockIdx.x * 128, h = blockIdx.y, b = blockIdx.z;

    const float* qbase = Q + ((size_t)b * SS + qt) * DD + h * DH;
    const float* kbase = K + (size_t)b * kv_bstride + h * DH;
    const float* vbase = V + (size_t)b * kv_bstride + h * DH;

    const int prow = tid >> 4;            // 0..15 (KV row within chunk, x4)
    const int pcol = (tid & 15) * 4;      // 0..60

    // ---- prefetch chunk 0 K/V into registers ----
    float4 pk[4], pv[4];
    #pragma unroll
    for (int u = 0; u < 4; ++u) {
        const int row = prow + 16 * u;
        pk[u] = *(const float4*)&kbase[(size_t)row * DD + pcol];
        pv[u] = *(const float4*)&vbase[(size_t)row * DD + pcol];
    }

    // ---- stage Q (pre-scaled by 1/8) as A-operand blocks ----
    #pragma unroll
    for (int u = 0; u < 8; ++u) {
        const int idx = tid + 256 * u;
        const int row = idx >> 4, colb = (idx & 15) * 4;
        float4 qv = *(const float4*)&qbase[(size_t)row * DD + colb];
        const int blk  = (row >> 4) * 8 + (colb >> 3);
        const int reg  = ((row & 15) >> 3) + 2 * ((colb & 7) >> 2);
        const int base = (row & 7) * 16 + reg;
        const int s    = (blk & 7) * 4;
        const float f[4] = {qv.x, qv.y, qv.z, qv.w};
        #pragma unroll
        for (int i = 0; i < 4; ++i)
            sQ[blk * 128 + ((base + i * 4) ^ s)] = f2tf32(f[i] * 0.125f);
    }

    float m0 = -1e30f, m1 = -1e30f, l0 = 0.0f, l1 = 0.0f;
    float oacc[8][4] = {};
    const int r0 = lane >> 2;        // fragment row within m16 (0..7)
    const int c0 = (lane & 3) * 2;   // fragment col within n8 (accum)

    for (int kt = 0; kt < Skv; kt += 64) {
        __syncthreads();             // prev PV readers done with sK/sV
        // ---- stage prefetched K (B: n=key, k=dh) and V (B: n=dh, k=key) ----
        #pragma unroll
        for (int u = 0; u < 4; ++u) {
            const int row  = prow + 16 * u;
            const int colb = pcol;
            {   // K
                const int blk  = (row >> 3) * 8 + (colb >> 3);
                const int s    = (blk & 7) * 4;
                const int base = (row & 7) * 8 + ((colb & 7) >> 2);
                const float f[4] = {pk[u].x, pk[u].y, pk[u].z, pk[u].w};
                #pragma unroll
                for (int i = 0; i < 4; ++i)
                    sK[blk * 64 + ((base + 2 * i) ^ s)] = f2tf32(f[i]);
            }
            {   // V transposed: element (n=col, k=row)
                const int kb    = row >> 3;
                const int s     = kb * 4;
                const int off_k = (row & 3) * 2 + ((row & 7) >> 2);
                const float f[4] = {pv[u].x, pv[u].y, pv[u].z, pv[u].w};
                #pragma unroll
                for (int i = 0; i < 4; ++i) {
                    const int c = colb + i;
                    sV[((c >> 3) * 8 + kb) * 64 + (((c & 7) * 8 + off_k) ^ s)] = f2tf32(f[i]);
                }
            }
        }
        __syncthreads();

        // ---- issue next chunk's K/V loads (latency hidden by compute below) ----
        if (kt + 64 < Skv) {
            #pragma unroll
            for (int u = 0; u < 4; ++u) {
                const int row = kt + 64 + prow + 16 * u;
                pk[u] = *(const float4*)&kbase[(size_t)row * DD + pcol];
                pv[u] = *(const float4*)&vbase[(size_t)row * DD + pcol];
            }
        }

        // ---- QK^T: 16 q x 64 keys per warp ----
        float sacc[8][4] = {};
        #pragma unroll
        for (int kb = 0; kb < 8; ++kb) {
            const int sa = kb * 4;
            uint4 af = *(const uint4*)&sQ[(w * 8 + kb) * 128 + ((lane * 4) ^ sa)];
            #pragma unroll
            for (int j = 0; j < 8; ++j) {
                uint2 bf = *(const uint2*)&sK[(j * 8 + kb) * 64 + ((lane * 2) ^ sa)];
                MMA_TF32(sacc[j], af, bf);
            }
        }

        // ---- band bias (additive +1 inside |dq|<=R) ----
        if (band) {
            const int q0 = qt + w * 16 + r0;
            #pragma unroll
            for (int j = 0; j < 8; ++j) {
                const int kc = kt + j * 8 + c0;
                #pragma unroll
                for (int v = 0; v < 4; ++v) {
                    const int dq = (q0 + ((v >> 1) << 3)) - (kc + (v & 1));
                    if ((unsigned)(dq + RR) <= 2u * RR) sacc[j][v] += 1.0f;
                }
            }
        }

        // ---- online softmax (rows r0, r0+8; cols across 4-lane group) ----
        float mx0 = -1e30f, mx1 = -1e30f;
        #pragma unroll
        for (int j = 0; j < 8; ++j) {
            mx0 = fmaxf(mx0, fmaxf(sacc[j][0], sacc[j][1]));
            mx1 = fmaxf(mx1, fmaxf(sacc[j][2], sacc[j][3]));
        }
        #pragma unroll
        for (int off = 1; off < 4; off <<= 1) {
            mx0 = fmaxf(mx0, __shfl_xor_sync(0xffffffffu, mx0, off, 4));
            mx1 = fmaxf(mx1, __shfl_xor_sync(0xffffffffu, mx1, off, 4));
        }
        const float mn0 = fmaxf(m0, mx0), mn1 = fmaxf(m1, mx1);
        const float cr0 = __expf(m0 - mn0), cr1 = __expf(m1 - mn1);
        float rs0 = 0.0f, rs1 = 0.0f;
        #pragma unroll
        for (int j = 0; j < 8; ++j) {
            sacc[j][0] = __expf(sacc[j][0] - mn0); rs0 += sacc[j][0];
            sacc[j][1] = __expf(sacc[j][1] - mn0); rs0 += sacc[j][1];
            sacc[j][2] = __expf(sacc[j][2] - mn1); rs1 += sacc[j][2];
            sacc[j][3] = __expf(sacc[j][3] - mn1); rs1 += sacc[j][3];
        }
        #pragma unroll
        for (int off = 1; off < 4; off <<= 1) {
            rs0 += __shfl_xor_sync(0xffffffffu, rs0, off, 4);
            rs1 += __shfl_xor_sync(0xffffffffu, rs1, off, 4);
        }
        l0 = l0 * cr0 + rs0; l1 = l1 * cr1 + rs1;
        m0 = mn0; m1 = mn1;
        #pragma unroll
        for (int j = 0; j < 8; ++j) {
            oacc[j][0] *= cr0; oacc[j][1] *= cr0;
            oacc[j][2] *= cr1; oacc[j][3] *= cr1;
        }

        // ---- store P as A-operand (warp-private blocks) ----
        #pragma unroll
        for (int j = 0; j < 8; ++j) {
            const int s = j * 4;
            const int base0 = r0 * 16 + 4 * (c0 & 3) + 2 * (c0 >> 2);
            const int o0 = base0 ^ s;
            const int o1 = (base0 + 4) ^ s;
            uint32_t* bp = &sP[(w * 8 + j) * 128];
            bp[o0]     = f2tf32(sacc[j][0]);
            bp[o0 + 1] = f2tf32(sacc[j][2]);
            bp[o1]     = f2tf32(sacc[j][1]);
            bp[o1 + 1] = f2tf32(sacc[j][3]);
        }
        __syncwarp();

        // ---- PV: o += P @ V ----
        #pragma unroll
        for (int kb = 0; kb < 8; ++kb) {
            const int sa = kb * 4;
            uint4 af = *(const uint4*)&sP[(w * 8 + kb) * 128 + ((lane * 4) ^ sa)];
            #pragma unroll
            for (int j = 0; j < 8; ++j) {
                uint2 bf = *(const uint2*)&sV[(j * 8 + kb) * 64 + ((lane * 2) ^ sa)];
                MMA_TF32(oacc[j], af, bf);
            }
        }
    }

    // ---- epilogue: normalize and store ----
    const float inv0 = 1.0f / l0, inv1 = 1.0f / l1;
    const size_t grow = (size_t)b * SS + qt + w * 16 + r0;
    #pragma unroll
    for (int j = 0; j < 8; ++j) {
        const int col = h * DH + j * 8 + c0;
        *(float2*)&O[grow * DD + col] =
            make_float2(oacc[j][0] * inv0, oacc[j][1] * inv0);
        *(float2*)&O[(grow + 8) * DD + col] =
            make_float2(oacc[j][2] * inv1, oacc[j][3] * inv1);
    }
}

// ---------------- row LayerNorm over D=768 ----------------
__global__ __launch_bounds__(256) void ln_kernel(
    const float* __restrict__ X, const float* __restrict__ gg,
    const float* __restrict__ bb, float* __restrict__ Y)
{
    __shared__ float red[9];
    const int row = blockIdx.x, tid = threadIdx.x;
    const float* x = X + (size_t)row * DD;
    float v0 = x[tid], v1 = x[tid + 256], v2 = x[tid + 512];

    float s = v0 + v1 + v2;
    #pragma unroll
    for (int off = 16; off; off >>= 1) s += __shfl_xor_sync(0xffffffffu, s, off);
    if ((tid & 31) == 0) red[tid >> 5] = s;
    __syncthreads();
    if (tid == 0) { float t = 0; for (int i = 0; i < 8; i++) t += red[i]; red[8] = t; }
    __syncthreads();
    const float mean = red[8] * (1.0f / 768.0f);

    float d0 = v0 - mean, d1 = v1 - mean, d2 = v2 - mean;
    float s2 = d0 * d0 + d1 * d1 + d2 * d2;
    #pragma unroll
    for (int off = 16; off; off >>= 1) s2 += __shfl_xor_sync(0xffffffffu, s2, off);
    __syncthreads();
    if ((tid & 31) == 0) red[tid >> 5] = s2;
    __syncthreads();
    if (tid == 0) { float t = 0; for (int i = 0; i < 8; i++) t += red[i]; red[8] = t; }
    __syncthreads();
    const float rstd = rsqrtf(red[8] * (1.0f / 768.0f) + 1e-12f);

    float* y = Y + (size_t)row * DD;
    y[tid]       = d0 * rstd * gg[tid]       + bb[tid];
    y[tid + 256] = d1 * rstd * gg[tid + 256] + bb[tid + 256];
    y[tid + 512] = d2 * rstd * gg[tid + 512] + bb[tid + 512];
}

// ---------------- host launcher ----------------
extern "C" void kernel_launch(void* const* d_in, const int* in_sizes, int n_in,
                              void* d_out, int out_size)
{
    const float* X      = (const float*)d_in[0];
    const float* tag    = (const float*)d_in[1];
    const float* sa_wq  = (const float*)d_in[2];  const float* sa_bq = (const float*)d_in[3];
    const float* sa_wk  = (const float*)d_in[4];  const float* sa_bk = (const float*)d_in[5];
    const float* sa_wv  = (const float*)d_in[6];  const float* sa_bv = (const float*)d_in[7];
    const float* sa_wo  = (const float*)d_in[8];  const float* sa_bo = (const float*)d_in[9];
    const float* sa_lg  = (const float*)d_in[10]; const float* sa_lb = (const float*)d_in[11];
    const float* ca_wq  = (const float*)d_in[12]; const float* ca_bq = (const float*)d_in[13];
    const float* ca_wk  = (const float*)d_in[14]; const float* ca_bk = (const float*)d_in[15];
    const float* ca_wv  = (const float*)d_in[16]; const float* ca_bv = (const float*)d_in[17];
    const float* ca_wo  = (const float*)d_in[18]; const float* ca_bo = (const float*)d_in[19];
    const float* ca_lg  = (const float*)d_in[20]; const float* ca_lb = (const float*)d_in[21];
    const float* ff_w1  = (const float*)d_in[22]; const float* ff_b1 = (const float*)d_in[23];
    const float* ff_w2  = (const float*)d_in[24]; const float* ff_b2 = (const float*)d_in[25];
    const float* ff_lg  = (const float*)d_in[26]; const float* ff_lb = (const float*)d_in[27];

    float *q, *k, *v, *ctx, *tmp, *x1, *x2, *tk, *tv, *it, *wt;
    cudaGetSymbolAddress((void**)&q,   g_q);
    cudaGetSymbolAddress((void**)&k,   g_k);
    cudaGetSymbolAddress((void**)&v,   g_v);
    cudaGetSymbolAddress((void**)&ctx, g_ctx);
    cudaGetSymbolAddress((void**)&tmp, g_tmp);
    cudaGetSymbolAddress((void**)&x1,  g_x1);
    cudaGetSymbolAddress((void**)&x2,  g_x2);
    cudaGetSymbolAddress((void**)&tk,  g_tagk);
    cudaGetSymbolAddress((void**)&tv,  g_tagv);
    cudaGetSymbolAddress((void**)&it,  g_int);
    cudaGetSymbolAddress((void**)&wt,  g_wt);

    const size_t WSZ = (size_t)DD * DD;
    float* wtq   = wt;
    float* wtk   = wt + WSZ;
    float* wtv   = wt + 2 * WSZ;
    float* wto   = wt + 3 * WSZ;
    float* wtcq  = wt + 4 * WSZ;
    float* wtcao = wt + 5 * WSZ;
    float* wtff1 = wt + 6 * WSZ;
    float* wtff2 = wtff1 + (size_t)FF * DD;

    cudaFuncSetAttribute((const void*)tgemm_kernel<0>, cudaFuncAttributeMaxDynamicSharedMemorySize, DSMEM_B);
    cudaFuncSetAttribute((const void*)tgemm_kernel<1>, cudaFuncAttributeMaxDynamicSharedMemorySize, DSMEM_B);
    cudaFuncSetAttribute((const void*)tgemm_kernel<2>, cudaFuncAttributeMaxDynamicSharedMemorySize, DSMEM_B);
    cudaFuncSetAttribute((const void*)attn_mma_kernel,  cudaFuncAttributeMaxDynamicSharedMemorySize, ASM_B);

    // ---- weight transposes ([K,N] -> [N,K]) ----
    const dim3 tb(32, 8);
    transpose_kernel<<<dim3(DD/32, DD/32), tb>>>(sa_wq, wtq,   DD, DD);
    transpose_kernel<<<dim3(DD/32, DD/32), tb>>>(sa_wk, wtk,   DD, DD);
    transpose_kernel<<<dim3(DD/32, DD/32), tb>>>(sa_wv, wtv,   DD, DD);
    transpose_kernel<<<dim3(DD/32, DD/32), tb>>>(sa_wo, wto,   DD, DD);
    transpose_kernel<<<dim3(DD/32, DD/32), tb>>>(ca_wq, wtcq,  DD, DD);
    transpose_kernel<<<dim3(DD/32, DD/32), tb>>>(ca_wo, wtcao, DD, DD);
    transpose_kernel<<<dim3(FF/32, DD/32), tb>>>(ff_w1, wtff1, DD, FF);
    transpose_kernel<<<dim3(DD/32, FF/32), tb>>>(ff_w2, wtff2, FF, DD);

    const dim3 gp (DD / 128, MR / 128);          // (6, 32)
    const dim3 gf (FF / 128, MR / 128);          // (24, 32)
    const dim3 gtag(DD / 64, 1);
    const dim3 gat (SS / 128, HH, BB);           // (16, 12, 2)

    // ---- self attention ----
    tgemm_kernel<0><<<gp, 256, DSMEM_B>>>(X,  wtq, sa_bq, nullptr, q, MR, DD, DD);
    tgemm_kernel<0><<<gp, 256, DSMEM_B>>>(X,  wtk, sa_bk, nullptr, k, MR, DD, DD);
    tgemm_kernel<0><<<gp, 256, DSMEM_B>>>(X,  wtv, sa_bv, nullptr, v, MR, DD, DD);
    attn_mma_kernel<<<gat, 256, ASM_B>>>(q, k, v, ctx, SS, (long long)SS * DD, 1);
    tgemm_kernel<2><<<gp, 256, DSMEM_B>>>(ctx, wto, sa_bo, X, tmp, MR, DD, DD);
    ln_kernel<<<MR, 256>>>(tmp, sa_lg, sa_lb, x1);

    // ---- cross attention (tags shared across batch) ----
    tgemm_kernel<0><<<gp, 256, DSMEM_B>>>(x1, wtcq, ca_bq, nullptr, q, MR, DD, DD);
    sgemm_kernel<0><<<gtag, 256>>>(tag, ca_wk, ca_bk, nullptr, tk, TT, DD, DD);
    sgemm_kernel<0><<<gtag, 256>>>(tag, ca_wv, ca_bv, nullptr, tv, TT, DD, DD);
    attn_mma_kernel<<<gat, 256, ASM_B>>>(q, tk, tv, ctx, TT, 0LL, 0);
    tgemm_kernel<2><<<gp, 256, DSMEM_B>>>(ctx, wtcao, ca_bo, x1, tmp, MR, DD, DD);
    ln_kernel<<<MR, 256>>>(tmp, ca_lg, ca_lb, x2);

    // ---- FFN ----
    tgemm_kernel<1><<<gf, 256, DSMEM_B>>>(x2, wtff1, ff_b1, nullptr, it, MR, FF, DD);
    tgemm_kernel<2><<<gp, 256, DSMEM_B>>>(it, wtff2, ff_b2, x2, tmp, MR, DD, FF);
    ln_kernel<<<MR, 256>>>(tmp, ff_lg, ff_lb, (float*)d_out);
}

// round 17
// speedup vs baseline: 1.5225x; 1.0400x over previous
#include <cuda_runtime.h>
#include <math.h>
#include <stdint.h>

#define BB   2
#define SS   2048
#define DD   768
#define HH   12
#define DH   64
#define TT   64
#define RR   50
#define MR   (BB*SS)      /* 4096 rows */
#define FF   3072

// dynamic smem for tgemm: 2 x (A 4096 + B 4096) uints
#define AREG 4096
#define DSMEM_U (4*AREG)
#define DSMEM_B (DSMEM_U*4)

// attention smem: Q 8192 + K 4096 + V 4096 + P 8192 uints = 96KB
#define ASM_U  24576
#define ASM_B  (ASM_U*4)

// ---------------- scratch (static device arrays, allowed) ----------------
__device__ float g_q   [MR*DD];
__device__ float g_k   [MR*DD];
__device__ float g_v   [MR*DD];
__device__ float g_ctx [MR*DD];
__device__ float g_tmp [MR*DD];
__device__ float g_x1  [MR*DD];
__device__ float g_x2  [MR*DD];
__device__ float g_tagk[TT*DD];
__device__ float g_tagv[TT*DD];
__device__ float g_int [MR*FF];
__device__ float g_wt  [6*DD*DD + 2*DD*FF];   // transposed tf32-rounded weights

static __device__ __forceinline__ uint32_t f2tf32(float x) {
    uint32_t y;
    asm("cvt.rna.tf32.f32 %0, %1;" : "=r"(y) : "f"(x));
    return y;
}

#define MMA_TF32(d, a, b) \
    asm volatile( \
        "mma.sync.aligned.m16n8k8.row.col.f32.tf32.tf32.f32 " \
        "{%0,%1,%2,%3}, {%4,%5,%6,%7}, {%8,%9}, {%0,%1,%2,%3};" \
        : "+f"((d)[0]), "+f"((d)[1]), "+f"((d)[2]), "+f"((d)[3]) \
        : "r"((a).x), "r"((a).y), "r"((a).z), "r"((a).w), \
          "r"((b).x), "r"((b).y))

// Stage one 128x32 A chunk + 128x32 B chunk into fragment-permuted smem.
// A block (m16 x k8) = 128 uints at blk*128, intra-block offset XOR (blk&7)*4.
// B block (n8 x k8) = 64 uints at blk*64, same XOR swizzle.
// tf32 truncation path: raw fp32 bits (HW reads top 19 bits); weights are
// pre-rounded rna in the transpose pre-pass.
static __device__ __forceinline__ void stage_chunk(
    uint32_t* __restrict__ sAp, uint32_t* __restrict__ sBp,
    const float4* ra, const float4* rb, int tid)
{
    #pragma unroll
    for (int u = 0; u < 4; ++u) {
        const int idx  = tid + 256 * u;
        const int row  = idx >> 3;            // 0..127
        const int colb = (idx & 7) * 4;       // 0,4,...,28
        {   // A: fragment m16n8k8, 4 regs/lane
            const int blk   = (row >> 4) * 4 + (colb >> 3);
            const int reg   = ((row & 15) >> 3) + 2 * ((colb & 7) >> 2);
            const int rbase = (row & 7) * 16 + reg;
            const int s     = (blk & 7) * 4;
            const float fv[4] = {ra[u].x, ra[u].y, ra[u].z, ra[u].w};
            #pragma unroll
            for (int i = 0; i < 4; ++i)
                sAp[blk * 128 + ((rbase + i * 4) ^ s)] = __float_as_uint(fv[i]);
        }
        {   // B: 2 regs/lane
            const int blk   = (row >> 3) * 4 + (colb >> 3);
            const int reg   = (colb & 7) >> 2;
            const int rbase = (row & 7) * 8 + reg;
            const int s     = (blk & 7) * 4;
            const float fv[4] = {rb[u].x, rb[u].y, rb[u].z, rb[u].w};
            #pragma unroll
            for (int i = 0; i < 4; ++i)
                sBp[blk * 64 + ((rbase + i * 2) ^ s)] = __float_as_uint(fv[i]);
        }
    }
}

// ---------------- weight transpose: W[K,N] -> Wt[N,K], tf32-rounded ----------------
struct TP6 { const float* src[6]; float* dst[6]; };

__global__ __launch_bounds__(256) void transpose6_kernel(TP6 p)
{
    __shared__ float t[32][33];
    const float* __restrict__ W  = p.src[blockIdx.z];
    float* __restrict__       Wt = p.dst[blockIdx.z];
    const int kb = blockIdx.y * 32, nb = blockIdx.x * 32;
    const int x = threadIdx.x, y = threadIdx.y;
    #pragma unroll
    for (int dy = 0; dy < 32; dy += 8)
        t[y + dy][x] = W[(size_t)(kb + y + dy) * DD + nb + x];
    __syncthreads();
    #pragma unroll
    for (int dy = 0; dy < 32; dy += 8)
        Wt[(size_t)(nb + y + dy) * DD + kb + x] = __uint_as_float(f2tf32(t[x][y + dy]));
}

__global__ __launch_bounds__(256) void transpose_kernel(
    const float* __restrict__ W, float* __restrict__ Wt, int K, int N)
{
    __shared__ float t[32][33];
    const int kb = blockIdx.y * 32, nb = blockIdx.x * 32;
    const int x = threadIdx.x, y = threadIdx.y;
    #pragma unroll
    for (int dy = 0; dy < 32; dy += 8)
        t[y + dy][x] = W[(size_t)(kb + y + dy) * N + nb + x];
    __syncthreads();
    #pragma unroll
    for (int dy = 0; dy < 32; dy += 8)
        Wt[(size_t)(nb + y + dy) * K + kb + x] = __uint_as_float(f2tf32(t[x][y + dy]));
}

// ---------------- tf32 mma.sync GEMM: C = A[MxK] @ Wt[NxK]^T + bias (+epi) ----------------
// Single barrier per K-chunk: stage(np) writes the buffer last read at c-1,
// and every warp's compute(c-1) precedes the end-of-iteration barrier of c-1,
// so the pre-stage barrier is provably redundant and removed.
template<int EPI>
__global__ __launch_bounds__(256) void tgemm_kernel(
    const float* __restrict__ A, const float* __restrict__ Wt,
    const float* __restrict__ bias, const float* __restrict__ res,
    float* __restrict__ C, int M, int N, int K)
{
    extern __shared__ uint32_t smem_u[];
    uint32_t* sA[2] = { smem_u,            smem_u + AREG     };
    uint32_t* sB[2] = { smem_u + 2*AREG,   smem_u + 3*AREG   };

    const int tid  = threadIdx.x;
    const int wid  = tid >> 5, lane = tid & 31;
    const int bn   = blockIdx.x * 128, bm = blockIdx.y * 128;
    const int wm16 = (wid >> 2) * 4;
    const int wn8  = (wid & 3) * 4;

    float acc[4][4][4] = {};
    float4 ra[4], rb[4];

    const int NC = K / 32;

    #pragma unroll
    for (int u = 0; u < 4; ++u) {
        const int idx = tid + 256 * u;
        const int row = idx >> 3, col = (idx & 7) * 4;
        ra[u] = *(const float4*)&A [(size_t)(bm + row) * K + col];
        rb[u] = *(const float4*)&Wt[(size_t)(bn + row) * K + col];
    }
    stage_chunk(sA[0], sB[0], ra, rb, tid);
    __syncthreads();

    for (int c = 0; c < NC; ++c) {
        const int p = c & 1;
        if (c + 1 < NC) {
            const int k0 = (c + 1) * 32;
            #pragma unroll
            for (int u = 0; u < 4; ++u) {
                const int idx = tid + 256 * u;
                const int row = idx >> 3, col = (idx & 7) * 4;
                ra[u] = *(const float4*)&A [(size_t)(bm + row) * K + k0 + col];
                rb[u] = *(const float4*)&Wt[(size_t)(bn + row) * K + k0 + col];
            }
        }
        #pragma unroll
        for (int k8 = 0; k8 < 4; ++k8) {
            uint4 af[4]; uint2 bf[4];
            #pragma unroll
            for (int t = 0; t < 4; ++t) {
                const int blk = (wm16 + t) * 4 + k8;
                af[t] = *(const uint4*)&sA[p][blk * 128 + ((lane * 4) ^ ((blk & 7) * 4))];
            }
            #pragma unroll
            for (int t = 0; t < 4; ++t) {
                const int blk = (wn8 + t) * 4 + k8;
                bf[t] = *(const uint2*)&sB[p][blk * 64 + ((lane * 2) ^ ((blk & 7) * 4))];
            }
            #pragma unroll
            for (int i = 0; i < 4; ++i)
                #pragma unroll
                for (int j = 0; j < 4; ++j)
                    MMA_TF32(acc[i][j], af[i], bf[j]);
        }
        if (c + 1 < NC) {
            stage_chunk(sA[(c + 1) & 1], sB[(c + 1) & 1], ra, rb, tid);
            __syncthreads();
        }
    }

    #pragma unroll
    for (int i = 0; i < 4; ++i) {
        const int r0 = bm + (wid >> 2) * 64 + i * 16 + (lane >> 2);
        #pragma unroll
        for (int j = 0; j < 4; ++j) {
            const int cb = bn + (wid & 3) * 32 + j * 8 + (lane & 3) * 2;
            float v0 = acc[i][j][0] + bias[cb];
            float v1 = acc[i][j][1] + bias[cb + 1];
            float v2 = acc[i][j][2] + bias[cb];
            float v3 = acc[i][j][3] + bias[cb + 1];
            if (EPI == 1) {
                v0 = 0.5f * v0 * (1.0f + erff(v0 * 0.70710678118654752f));
                v1 = 0.5f * v1 * (1.0f + erff(v1 * 0.70710678118654752f));
                v2 = 0.5f * v2 * (1.0f + erff(v2 * 0.70710678118654752f));
                v3 = 0.5f * v3 * (1.0f + erff(v3 * 0.70710678118654752f));
            }
            if (EPI == 2) {
                v0 += res[(size_t)r0 * N + cb];
                v1 += res[(size_t)r0 * N + cb + 1];
                v2 += res[(size_t)(r0 + 8) * N + cb];
                v3 += res[(size_t)(r0 + 8) * N + cb + 1];
            }
            *(float2*)&C[(size_t)r0 * N + cb]       = make_float2(v0, v1);
            *(float2*)&C[(size_t)(r0 + 8) * N + cb] = make_float2(v2, v3);
        }
    }
}

// ---------------- small fp32 SGEMM (tag K/V projections only) ----------------
template<int EPI>
__global__ __launch_bounds__(256) void sgemm_kernel(
    const float* __restrict__ A, const float* __restrict__ W,
    const float* __restrict__ bias, const float* __restrict__ res,
    float* __restrict__ C, int M, int N, int K)
{
    __shared__ float As[16][64];
    __shared__ float Bs[16][64];
    const int tid = threadIdx.x;
    const int tx = tid & 15, ty = tid >> 4;
    const int bn = blockIdx.x * 64, bm = blockIdx.y * 64;
    const int am = tid >> 2, ak = (tid & 3) * 4;
    const int wk = tid >> 4, wn = (tid & 15) * 4;
    float acc[4][4] = {};
    for (int k0 = 0; k0 < K; k0 += 16) {
        float4 av = *(const float4*)&A[(size_t)(bm + am) * K + k0 + ak];
        As[ak + 0][am] = av.x; As[ak + 1][am] = av.y;
        As[ak + 2][am] = av.z; As[ak + 3][am] = av.w;
        *(float4*)&Bs[wk][wn] = *(const float4*)&W[(size_t)(k0 + wk) * N + bn + wn];
        __syncthreads();
        #pragma unroll
        for (int kk = 0; kk < 16; kk++) {
            float4 a4 = *(const float4*)&As[kk][ty * 4];
            float4 b4 = *(const float4*)&Bs[kk][tx * 4];
            float a[4] = {a4.x, a4.y, a4.z, a4.w};
            float b[4] = {b4.x, b4.y, b4.z, b4.w};
            #pragma unroll
            for (int i = 0; i < 4; i++)
                #pragma unroll
                for (int j = 0; j < 4; j++)
                    acc[i][j] = fmaf(a[i], b[j], acc[i][j]);
        }
        __syncthreads();
    }
    #pragma unroll
    for (int i = 0; i < 4; i++) {
        const int m = bm + ty * 4 + i;
        #pragma unroll
        for (int j = 0; j < 4; j++) {
            const int n = bn + tx * 4 + j;
            float v = acc[i][j] + bias[n];
            if (EPI == 1) v = 0.5f * v * (1.0f + erff(v * 0.70710678118654752f));
            if (EPI == 2) v += res[(size_t)m * N + n];
            C[(size_t)m * N + n] = v;
        }
    }
}

// ---------------- tensor-core flash attention (with K/V prefetch) ----------------
// 128-query tile per CTA, 8 warps; warp w owns m16 tile w (16 q rows x all keys).
// Key chunks of 64. QK^T and PV via tf32 m16n8k8; online softmax on fragments.
// Next chunk's K/V global loads are issued right after staging so compute hides them.
// Both barriers here are load-bearing (sK/sV are single-buffered).
__global__ __launch_bounds__(256) void attn_mma_kernel(
    const float* __restrict__ Q, const float* __restrict__ K,
    const float* __restrict__ V, float* __restrict__ O,
    int Skv, long long kv_bstride, int band)
{
    extern __shared__ uint32_t sm[];
    uint32_t* sQ = sm;               // 8 m-blk x 8 k-blk x 128 = 8192
    uint32_t* sK = sm + 8192;        // 8 n-blk x 8 k-blk x 64  = 4096
    uint32_t* sV = sm + 12288;       // 4096
    uint32_t* sP = sm + 16384;       // 8192

    const int tid = threadIdx.x, w = tid >> 5, lane = tid & 31;
    const int qt = blockIdx.x * 128, h = blockIdx.y, b = blockIdx.z;

    const float* qbase = Q + ((size_t)b * SS + qt) * DD + h * DH;
    const float* kbase = K + (size_t)b * kv_bstride + h * DH;
    const float* vbase = V + (size_t)b * kv_bstride + h * DH;

    const int prow = tid >> 4;            // 0..15 (KV row within chunk, x4)
    const int pcol = (tid & 15) * 4;      // 0..60

    // ---- prefetch chunk 0 K/V into registers ----
    float4 pk[4], pv[4];
    #pragma unroll
    for (int u = 0; u < 4; ++u) {
        const int row = prow + 16 * u;
        pk[u] = *(const float4*)&kbase[(size_t)row * DD + pcol];
        pv[u] = *(const float4*)&vbase[(size_t)row * DD + pcol];
    }

    // ---- stage Q (pre-scaled by 1/8) as A-operand blocks ----
    #pragma unroll
    for (int u = 0; u < 8; ++u) {
        const int idx = tid + 256 * u;
        const int row = idx >> 4, colb = (idx & 15) * 4;
        float4 qv = *(const float4*)&qbase[(size_t)row * DD + colb];
        const int blk  = (row >> 4) * 8 + (colb >> 3);
        const int reg  = ((row & 15) >> 3) + 2 * ((colb & 7) >> 2);
        const int base = (row & 7) * 16 + reg;
        const int s    = (blk & 7) * 4;
        const float f[4] = {qv.x, qv.y, qv.z, qv.w};
        #pragma unroll
        for (int i = 0; i < 4; ++i)
            sQ[blk * 128 + ((base + i * 4) ^ s)] = __float_as_uint(f[i] * 0.125f);
    }

    float m0 = -1e30f, m1 = -1e30f, l0 = 0.0f, l1 = 0.0f;
    float oacc[8][4] = {};
    const int r0 = lane >> 2;        // fragment row within m16 (0..7)
    const int c0 = (lane & 3) * 2;   // fragment col within n8 (accum)

    for (int kt = 0; kt < Skv; kt += 64) {
        __syncthreads();             // prev PV readers done with sK/sV
        // ---- stage prefetched K (B: n=key, k=dh) and V (B: n=dh, k=key) ----
        #pragma unroll
        for (int u = 0; u < 4; ++u) {
            const int row  = prow + 16 * u;
            const int colb = pcol;
            {   // K
                const int blk  = (row >> 3) * 8 + (colb >> 3);
                const int s    = (blk & 7) * 4;
                const int base = (row & 7) * 8 + ((colb & 7) >> 2);
                const float f[4] = {pk[u].x, pk[u].y, pk[u].z, pk[u].w};
                #pragma unroll
                for (int i = 0; i < 4; ++i)
                    sK[blk * 64 + ((base + 2 * i) ^ s)] = __float_as_uint(f[i]);
            }
            {   // V transposed: element (n=col, k=row)
                const int kb    = row >> 3;
                const int s     = kb * 4;
                const int off_k = (row & 3) * 2 + ((row & 7) >> 2);
                const float f[4] = {pv[u].x, pv[u].y, pv[u].z, pv[u].w};
                #pragma unroll
                for (int i = 0; i < 4; ++i) {
                    const int c = colb + i;
                    sV[((c >> 3) * 8 + kb) * 64 + (((c & 7) * 8 + off_k) ^ s)] = __float_as_uint(f[i]);
                }
            }
        }
        __syncthreads();

        // ---- issue next chunk's K/V loads (latency hidden by compute below) ----
        if (kt + 64 < Skv) {
            #pragma unroll
            for (int u = 0; u < 4; ++u) {
                const int row = kt + 64 + prow + 16 * u;
                pk[u] = *(const float4*)&kbase[(size_t)row * DD + pcol];
                pv[u] = *(const float4*)&vbase[(size_t)row * DD + pcol];
            }
        }

        // ---- QK^T: 16 q x 64 keys per warp ----
        float sacc[8][4] = {};
        #pragma unroll
        for (int kb = 0; kb < 8; ++kb) {
            const int sa = kb * 4;
            uint4 af = *(const uint4*)&sQ[(w * 8 + kb) * 128 + ((lane * 4) ^ sa)];
            #pragma unroll
            for (int j = 0; j < 8; ++j) {
                uint2 bf = *(const uint2*)&sK[(j * 8 + kb) * 64 + ((lane * 2) ^ sa)];
                MMA_TF32(sacc[j], af, bf);
            }
        }

        // ---- band bias (additive +1 inside |dq|<=R) ----
        if (band) {
            const int q0 = qt + w * 16 + r0;
            #pragma unroll
            for (int j = 0; j < 8; ++j) {
                const int kc = kt + j * 8 + c0;
                #pragma unroll
                for (int v = 0; v < 4; ++v) {
                    const int dq = (q0 + ((v >> 1) << 3)) - (kc + (v & 1));
                    if ((unsigned)(dq + RR) <= 2u * RR) sacc[j][v] += 1.0f;
                }
            }
        }

        // ---- online softmax (rows r0, r0+8; cols across 4-lane group) ----
        float mx0 = -1e30f, mx1 = -1e30f;
        #pragma unroll
        for (int j = 0; j < 8; ++j) {
            mx0 = fmaxf(mx0, fmaxf(sacc[j][0], sacc[j][1]));
            mx1 = fmaxf(mx1, fmaxf(sacc[j][2], sacc[j][3]));
        }
        #pragma unroll
        for (int off = 1; off < 4; off <<= 1) {
            mx0 = fmaxf(mx0, __shfl_xor_sync(0xffffffffu, mx0, off, 4));
            mx1 = fmaxf(mx1, __shfl_xor_sync(0xffffffffu, mx1, off, 4));
        }
        const float mn0 = fmaxf(m0, mx0), mn1 = fmaxf(m1, mx1);
        const float cr0 = __expf(m0 - mn0), cr1 = __expf(m1 - mn1);
        float rs0 = 0.0f, rs1 = 0.0f;
        #pragma unroll
        for (int j = 0; j < 8; ++j) {
            sacc[j][0] = __expf(sacc[j][0] - mn0); rs0 += sacc[j][0];
            sacc[j][1] = __expf(sacc[j][1] - mn0); rs0 += sacc[j][1];
            sacc[j][2] = __expf(sacc[j][2] - mn1); rs1 += sacc[j][2];
            sacc[j][3] = __expf(sacc[j][3] - mn1); rs1 += sacc[j][3];
        }
        #pragma unroll
        for (int off = 1; off < 4; off <<= 1) {
            rs0 += __shfl_xor_sync(0xffffffffu, rs0, off, 4);
            rs1 += __shfl_xor_sync(0xffffffffu, rs1, off, 4);
        }
        l0 = l0 * cr0 + rs0; l1 = l1 * cr1 + rs1;
        m0 = mn0; m1 = mn1;
        #pragma unroll
        for (int j = 0; j < 8; ++j) {
            oacc[j][0] *= cr0; oacc[j][1] *= cr0;
            oacc[j][2] *= cr1; oacc[j][3] *= cr1;
        }

        // ---- store P as A-operand (warp-private blocks) ----
        #pragma unroll
        for (int j = 0; j < 8; ++j) {
            const int s = j * 4;
            const int base0 = r0 * 16 + 4 * (c0 & 3) + 2 * (c0 >> 2);
            const int o0 = base0 ^ s;
            const int o1 = (base0 + 4) ^ s;
            uint32_t* bp = &sP[(w * 8 + j) * 128];
            bp[o0]     = __float_as_uint(sacc[j][0]);
            bp[o0 + 1] = __float_as_uint(sacc[j][2]);
            bp[o1]     = __float_as_uint(sacc[j][1]);
            bp[o1 + 1] = __float_as_uint(sacc[j][3]);
        }
        __syncwarp();

        // ---- PV: o += P @ V ----
        #pragma unroll
        for (int kb = 0; kb < 8; ++kb) {
            const int sa = kb * 4;
            uint4 af = *(const uint4*)&sP[(w * 8 + kb) * 128 + ((lane * 4) ^ sa)];
            #pragma unroll
            for (int j = 0; j < 8; ++j) {
                uint2 bf = *(const uint2*)&sV[(j * 8 + kb) * 64 + ((lane * 2) ^ sa)];
                MMA_TF32(oacc[j], af, bf);
            }
        }
    }

    // ---- epilogue: normalize and store ----
    const float inv0 = 1.0f / l0, inv1 = 1.0f / l1;
    const size_t grow = (size_t)b * SS + qt + w * 16 + r0;
    #pragma unroll
    for (int j = 0; j < 8; ++j) {
        const int col = h * DH + j * 8 + c0;
        *(float2*)&O[grow * DD + col] =
            make_float2(oacc[j][0] * inv0, oacc[j][1] * inv0);
        *(float2*)&O[(grow + 8) * DD + col] =
            make_float2(oacc[j][2] * inv1, oacc[j][3] * inv1);
    }
}

// ---------------- row LayerNorm over D=768 ----------------
__global__ __launch_bounds__(256) void ln_kernel(
    const float* __restrict__ X, const float* __restrict__ gg,
    const float* __restrict__ bb, float* __restrict__ Y)
{
    __shared__ float red[9];
    const int row = blockIdx.x, tid = threadIdx.x;
    const float* x = X + (size_t)row * DD;
    float v0 = x[tid], v1 = x[tid + 256], v2 = x[tid + 512];

    float s = v0 + v1 + v2;
    #pragma unroll
    for (int off = 16; off; off >>= 1) s += __shfl_xor_sync(0xffffffffu, s, off);
    if ((tid & 31) == 0) red[tid >> 5] = s;
    __syncthreads();
    if (tid == 0) { float t = 0; for (int i = 0; i < 8; i++) t += red[i]; red[8] = t; }
    __syncthreads();
    const float mean = red[8] * (1.0f / 768.0f);

    float d0 = v0 - mean, d1 = v1 - mean, d2 = v2 - mean;
    float s2 = d0 * d0 + d1 * d1 + d2 * d2;
    #pragma unroll
    for (int off = 16; off; off >>= 1) s2 += __shfl_xor_sync(0xffffffffu, s2, off);
    __syncthreads();
    if ((tid & 31) == 0) red[tid >> 5] = s2;
    __syncthreads();
    if (tid == 0) { float t = 0; for (int i = 0; i < 8; i++) t += red[i]; red[8] = t; }
    __syncthreads();
    const float rstd = rsqrtf(red[8] * (1.0f / 768.0f) + 1e-12f);

    float* y = Y + (size_t)row * DD;
    y[tid]       = d0 * rstd * gg[tid]       + bb[tid];
    y[tid + 256] = d1 * rstd * gg[tid + 256] + bb[tid + 256];
    y[tid + 512] = d2 * rstd * gg[tid + 512] + bb[tid + 512];
}

// ---------------- host launcher ----------------
extern "C" void kernel_launch(void* const* d_in, const int* in_sizes, int n_in,
                              void* d_out, int out_size)
{
    const float* X      = (const float*)d_in[0];
    const float* tag    = (const float*)d_in[1];
    const float* sa_wq  = (const float*)d_in[2];  const float* sa_bq = (const float*)d_in[3];
    const float* sa_wk  = (const float*)d_in[4];  const float* sa_bk = (const float*)d_in[5];
    const float* sa_wv  = (const float*)d_in[6];  const float* sa_bv = (const float*)d_in[7];
    const float* sa_wo  = (const float*)d_in[8];  const float* sa_bo = (const float*)d_in[9];
    const float* sa_lg  = (const float*)d_in[10]; const float* sa_lb = (const float*)d_in[11];
    const float* ca_wq  = (const float*)d_in[12]; const float* ca_bq = (const float*)d_in[13];
    const float* ca_wk  = (const float*)d_in[14]; const float* ca_bk = (const float*)d_in[15];
    const float* ca_wv  = (const float*)d_in[16]; const float* ca_bv = (const float*)d_in[17];
    const float* ca_wo  = (const float*)d_in[18]; const float* ca_bo = (const float*)d_in[19];
    const float* ca_lg  = (const float*)d_in[20]; const float* ca_lb = (const float*)d_in[21];
    const float* ff_w1  = (const float*)d_in[22]; const float* ff_b1 = (const float*)d_in[23];
    const float* ff_w2  = (const float*)d_in[24]; const float* ff_b2 = (const float*)d_in[25];
    const float* ff_lg  = (const float*)d_in[26]; const float* ff_lb = (const float*)d_in[27];

    float *q, *k, *v, *ctx, *tmp, *x1, *x2, *tk, *tv, *it, *wt;
    cudaGetSymbolAddress((void**)&q,   g_q);
    cudaGetSymbolAddress((void**)&k,   g_k);
    cudaGetSymbolAddress((void**)&v,   g_v);
    cudaGetSymbolAddress((void**)&ctx, g_ctx);
    cudaGetSymbolAddress((void**)&tmp, g_tmp);
    cudaGetSymbolAddress((void**)&x1,  g_x1);
    cudaGetSymbolAddress((void**)&x2,  g_x2);
    cudaGetSymbolAddress((void**)&tk,  g_tagk);
    cudaGetSymbolAddress((void**)&tv,  g_tagv);
    cudaGetSymbolAddress((void**)&it,  g_int);
    cudaGetSymbolAddress((void**)&wt,  g_wt);

    const size_t WSZ = (size_t)DD * DD;
    float* wtq   = wt;
    float* wtk   = wt + WSZ;
    float* wtv   = wt + 2 * WSZ;
    float* wto   = wt + 3 * WSZ;
    float* wtcq  = wt + 4 * WSZ;
    float* wtcao = wt + 5 * WSZ;
    float* wtff1 = wt + 6 * WSZ;
    float* wtff2 = wtff1 + (size_t)FF * DD;

    cudaFuncSetAttribute((const void*)tgemm_kernel<0>, cudaFuncAttributeMaxDynamicSharedMemorySize, DSMEM_B);
    cudaFuncSetAttribute((const void*)tgemm_kernel<1>, cudaFuncAttributeMaxDynamicSharedMemorySize, DSMEM_B);
    cudaFuncSetAttribute((const void*)tgemm_kernel<2>, cudaFuncAttributeMaxDynamicSharedMemorySize, DSMEM_B);
    cudaFuncSetAttribute((const void*)attn_mma_kernel,  cudaFuncAttributeMaxDynamicSharedMemorySize, ASM_B);

    // ---- weight transposes ([K,N] -> [N,K]) with tf32 pre-rounding ----
    const dim3 tb(32, 8);
    TP6 tp;
    tp.src[0] = sa_wq; tp.dst[0] = wtq;
    tp.src[1] = sa_wk; tp.dst[1] = wtk;
    tp.src[2] = sa_wv; tp.dst[2] = wtv;
    tp.src[3] = sa_wo; tp.dst[3] = wto;
    tp.src[4] = ca_wq; tp.dst[4] = wtcq;
    tp.src[5] = ca_wo; tp.dst[5] = wtcao;
    transpose6_kernel<<<dim3(DD/32, DD/32, 6), tb>>>(tp);
    transpose_kernel<<<dim3(FF/32, DD/32), tb>>>(ff_w1, wtff1, DD, FF);
    transpose_kernel<<<dim3(DD/32, FF/32), tb>>>(ff_w2, wtff2, FF, DD);

    const dim3 gp (DD / 128, MR / 128);          // (6, 32)
    const dim3 gf (FF / 128, MR / 128);          // (24, 32)
    const dim3 gtag(DD / 64, 1);
    const dim3 gat (SS / 128, HH, BB);           // (16, 12, 2)

    // ---- self attention ----
    tgemm_kernel<0><<<gp, 256, DSMEM_B>>>(X,  wtq, sa_bq, nullptr, q, MR, DD, DD);
    tgemm_kernel<0><<<gp, 256, DSMEM_B>>>(X,  wtk, sa_bk, nullptr, k, MR, DD, DD);
    tgemm_kernel<0><<<gp, 256, DSMEM_B>>>(X,  wtv, sa_bv, nullptr, v, MR, DD, DD);
    attn_mma_kernel<<<gat, 256, ASM_B>>>(q, k, v, ctx, SS, (long long)SS * DD, 1);
    tgemm_kernel<2><<<gp, 256, DSMEM_B>>>(ctx, wto, sa_bo, X, tmp, MR, DD, DD);
    ln_kernel<<<MR, 256>>>(tmp, sa_lg, sa_lb, x1);

    // ---- cross attention (tags shared across batch) ----
    tgemm_kernel<0><<<gp, 256, DSMEM_B>>>(x1, wtcq, ca_bq, nullptr, q, MR, DD, DD);
    sgemm_kernel<0><<<gtag, 256>>>(tag, ca_wk, ca_bk, nullptr, tk, TT, DD, DD);
    sgemm_kernel<0><<<gtag, 256>>>(tag, ca_wv, ca_bv, nullptr, tv, TT, DD, DD);
    attn_mma_kernel<<<gat, 256, ASM_B>>>(q, tk, tv, ctx, TT, 0LL, 0);
    tgemm_kernel<2><<<gp, 256, DSMEM_B>>>(ctx, wtcao, ca_bo, x1, tmp, MR, DD, DD);
    ln_kernel<<<MR, 256>>>(tmp, ca_lg, ca_lb, x2);

    // ---- FFN ----
    tgemm_kernel<1><<<gf,  256, DSMEM_B>>>(x2, wtff1, ff_b1, nullptr, it, MR, FF, DD);
    tgemm_kernel<2><<<gp, 256, DSMEM_B>>>(it, wtff2, ff_b2, x2, tmp, MR, DD, FF);
    ln_kernel<<<MR, 256>>>(tmp, ff_lg, ff_lb, (float*)d_out);
}